// round 16
// baseline (speedup 1.0000x reference)
#include <cuda_runtime.h>
#include <cuda_fp16.h>
#include <math.h>
#include <stdint.h>

// ---------------------------------------------------------------------------
// Problem constants
// ---------------------------------------------------------------------------
#define NN 20000
#define DD 128
#define HH 4
#define EE 80000
#define LLAYERS 2
#define HD (HH * DD)      // 512
#define LDC 1536          // fat projection width per node type

// Fat column layout (per node type X in {my, opp}):
//  [0,512)      GAT projection #1 (my: Wl_beats ; opp: Wr_beats)
//  [512,1024)   GAT projection #2 (my: Wr_rev   ; opp: Wl_rev)
//  [1024,1280)  CG lose, INTERLEAVED: group k (k=0..31) = 8 cols:
//               cols 1024+8k+{0..3} = Wf cols {4k..4k+3},
//               cols 1024+8k+{4..7} = Ws cols {4k..4k+3}
//               (my: src/bottom rows ; opp: dst/top rows + biases)
//  [1280,1536)  CG rev, same interleave (my: dst/top + biases ; opp: src/bottom)

// ---------------------------------------------------------------------------
// Static device scratch
// ---------------------------------------------------------------------------
__device__ __align__(16) __half g_C_my [(size_t)NN * LDC];   // fp16 fat features
__device__ __align__(16) __half g_C_opp[(size_t)NN * LDC];

__device__ __align__(16) float g_x_my [NN * DD];
__device__ __align__(16) float g_x_opp[NN * DD];

// fp16 feature operands (A side of GEMMs)
__device__ __align__(16) __half g_xh_my [NN * DD];
__device__ __align__(16) __half g_xh_opp[NN * DD];
__device__ __align__(16) __half g_ah_my [NN * DD];
__device__ __align__(16) __half g_ah_opp[NN * DD];

// fp16 weight operands (B side), K-MAJOR, DOUBLE-BUFFERED per layer
__device__ __align__(16) __half g_Wth_my [2][DD * LDC];
__device__ __align__(16) __half g_Wth_opp[2][DD * LDC];
__device__ __align__(16) __half g_nwWh   [2][DD * DD];
__device__ __align__(16) float g_bias_my [2][LDC];
__device__ __align__(16) float g_bias_opp[2][LDC];

// CSR (4 relations: 0=beats, 1=rev_loses, 2=loses, 3=rev_beats), built once
__device__ int g_row [4 * (NN + 1)];
__device__ int g_cnt [4 * NN];
__device__ int g_fill[4 * NN];
__device__ int g_srcs[4 * EE];

// ---------------------------------------------------------------------------
// Arg structs for merged launches
// ---------------------------------------------------------------------------
struct GemmArgs {
    const __half *Ah[2], *Bh[2];
    const float *bias[2];
    __half *Ch[2];     // fp16 C output (fat projections) -> stmatrix epilogue
    float  *Cf[2];     // fp32 C output (nodewise Linear) -> direct epilogue
    __half *Hout[2];   // fp16 feature copy (next-layer A)
    int M, ldc, ldb;
};

// Fused edge args: index = dst node type (0 = opp, 1 = my)
struct EdgeArgs {
    const __half *xl[2], *xr[2];
    const float *att[2];
    const int *growp[2], *gsrcs[2];
    const __half *Pd[2], *Ps[2];       // interleaved CG gate bases (dst, src)
    const int *crowp[2], *csrcs[2];
    const float *xres[2], *bias[2];
    __half *ah[2];
};

// ---------------------------------------------------------------------------
// Warp MMA / cp.async helpers
// ---------------------------------------------------------------------------
__device__ __forceinline__ uint32_t smem_to_u32(const void* p)
{
    uint32_t a;
    asm("{ .reg .u64 t; cvta.to.shared.u64 t, %1; cvt.u32.u64 %0, t; }"
        : "=r"(a) : "l"(p));
    return a;
}

__device__ __forceinline__ void ldx4(uint32_t* r, uint32_t addr)
{
    asm volatile("ldmatrix.sync.aligned.m8n8.x4.shared.b16 {%0,%1,%2,%3}, [%4];"
                 : "=r"(r[0]), "=r"(r[1]), "=r"(r[2]), "=r"(r[3]) : "r"(addr));
}

__device__ __forceinline__ void ldx4t(uint32_t* r, uint32_t addr)
{
    asm volatile("ldmatrix.sync.aligned.m8n8.x4.trans.shared.b16 {%0,%1,%2,%3}, [%4];"
                 : "=r"(r[0]), "=r"(r[1]), "=r"(r[2]), "=r"(r[3]) : "r"(addr));
}

__device__ __forceinline__ void stx4(uint32_t addr, uint32_t r0, uint32_t r1,
                                     uint32_t r2, uint32_t r3)
{
    asm volatile("stmatrix.sync.aligned.m8n8.x4.shared.b16 [%0], {%1,%2,%3,%4};"
                 :: "r"(addr), "r"(r0), "r"(r1), "r"(r2), "r"(r3) : "memory");
}

__device__ __forceinline__ void mma16816(float* c, const uint32_t* a,
                                         uint32_t b0, uint32_t b1)
{
    asm volatile(
        "mma.sync.aligned.m16n8k16.row.col.f32.f16.f16.f32 "
        "{%0,%1,%2,%3}, {%4,%5,%6,%7}, {%8,%9}, {%0,%1,%2,%3};"
        : "+f"(c[0]), "+f"(c[1]), "+f"(c[2]), "+f"(c[3])
        : "r"(a[0]), "r"(a[1]), "r"(a[2]), "r"(a[3]), "r"(b0), "r"(b1));
}

__device__ __forceinline__ void cpa16(uint32_t dst, const void* src, int sz)
{
    asm volatile("cp.async.cg.shared.global [%0], [%1], 16, %2;"
                 :: "r"(dst), "l"(src), "r"(sz));
}
#define CP_COMMIT() asm volatile("cp.async.commit_group;" ::: "memory")
#define CP_WAIT(n)  asm volatile("cp.async.wait_group %0;" :: "n"(n) : "memory")

__device__ __forceinline__ float4 half4_to_float4(uint2 v)
{
    __half2 h01 = *reinterpret_cast<__half2*>(&v.x);
    __half2 h23 = *reinterpret_cast<__half2*>(&v.y);
    float2 f0 = __half22float2(h01);
    float2 f1 = __half22float2(h23);
    return make_float4(f0.x, f0.y, f1.x, f1.y);
}

__device__ __forceinline__ void half8_to_float8(uint4 v, float* f)
{
    float4 a = half4_to_float4(make_uint2(v.x, v.y));
    float4 b = half4_to_float4(make_uint2(v.z, v.w));
    f[0] = a.x; f[1] = a.y; f[2] = a.z; f[3] = a.w;
    f[4] = b.x; f[5] = b.y; f[6] = b.z; f[7] = b.w;
}

// ---------------------------------------------------------------------------
// Tensor-core GEMM: C[M, col0..+128] = A[M,128] @ B[128, Nc] + bias.
// A row-major fp16; B K-MAJOR fp16 (ldb cols), loaded via ldmatrix.trans.
// BK=32 slabs, 2-stage cp.async ring, 32 KB smem.
// Ch path: stmatrix -> smem -> coalesced 128B stores.
// ---------------------------------------------------------------------------
#define SM_A  0
#define SM_B  8192
#define STAGE_BYTES 16384
#define DYN_SMEM 32768

__global__ void __launch_bounds__(256, 2)
mma_gemm(GemmArgs ga)
{
    extern __shared__ char smem[];
    const uint32_t sb = smem_to_u32(smem);

    const int z = blockIdx.z;
    const __half* __restrict__ Ah = ga.Ah[z];
    const __half* __restrict__ Bh = ga.Bh[z];
    const int M = ga.M, ldc = ga.ldc, ldb = ga.ldb;

    const int tid  = threadIdx.x;
    const int wid  = tid >> 5;
    const int lane = tid & 31;
    const int row0 = blockIdx.y * 128;
    const int col0 = blockIdx.x * 128;

    const int warp_m = (wid & 3) * 32;
    const int warp_n = (wid >> 2) * 64;

    float acc[2][8][4];
#pragma unroll
    for (int mt = 0; mt < 2; mt++)
#pragma unroll
        for (int nt = 0; nt < 8; nt++)
#pragma unroll
            for (int j = 0; j < 4; j++) acc[mt][nt][j] = 0.f;

    auto load_slab = [&](int slab, int buf) {
        const uint32_t bufb = sb + buf * STAGE_BYTES;
        const int kbase = slab * 32;
#pragma unroll
        for (int it = 0; it < 2; it++) {
            int c  = tid + it * 256;
            int r  = c >> 2;
            int ch = c & 3;
            uint32_t so = (uint32_t)r * 64 + (uint32_t)((ch ^ ((r >> 1) & 3)) * 16);
            int kc = kbase + ch * 8;
            int gr = row0 + r;
            int asz = (gr < M) ? 16 : 0;
            int gra = (gr < M) ? gr : 0;
            cpa16(bufb + SM_A + so, Ah + (size_t)gra * DD + kc, asz);
        }
#pragma unroll
        for (int it = 0; it < 2; it++) {
            int c  = tid + it * 256;
            int kr = c >> 4;
            int ch = c & 15;
            uint32_t so = (uint32_t)kr * 256 + (uint32_t)((ch ^ (kr & 7)) * 16);
            cpa16(bufb + SM_B + so,
                  Bh + (size_t)(kbase + kr) * ldb + col0 + ch * 8, 16);
        }
        CP_COMMIT();
    };

    auto comp_slab = [&](int buf) {
        const uint32_t bufb = sb + buf * STAGE_BYTES;
#pragma unroll
        for (int ks = 0; ks < 2; ks++) {
            uint32_t af[2][4];
#pragma unroll
            for (int mt = 0; mt < 2; mt++) {
                int r  = warp_m + mt * 16 + (lane & 7) + ((lane >> 3) & 1) * 8;
                int ch = ks * 2 + (lane >> 4);
                uint32_t off = (uint32_t)r * 64
                             + (uint32_t)((ch ^ ((r >> 1) & 3)) * 16);
                ldx4(af[mt], bufb + SM_A + off);
            }
            uint32_t bf[4][4];
#pragma unroll
            for (int np = 0; np < 4; np++) {
                int kr = ks * 16 + (lane & 7) + ((lane >> 3) & 1) * 8;
                int ch = (warp_n >> 3) + np * 2 + ((lane >> 4) & 1);
                uint32_t off = (uint32_t)kr * 256
                             + (uint32_t)((ch ^ (kr & 7)) * 16);
                ldx4t(bf[np], bufb + SM_B + off);
            }
#pragma unroll
            for (int mt = 0; mt < 2; mt++) {
#pragma unroll
                for (int nt = 0; nt < 8; nt++) {
                    int np = nt >> 1, hi = (nt & 1) * 2;
                    mma16816(acc[mt][nt], af[mt], bf[np][hi], bf[np][hi + 1]);
                }
            }
        }
    };

    load_slab(0, 0);
    load_slab(1, 1);
    CP_WAIT(1);
    __syncthreads();
    comp_slab(0);
    __syncthreads();
    load_slab(2, 0);
    CP_WAIT(1);
    __syncthreads();
    comp_slab(1);
    __syncthreads();
    load_slab(3, 1);
    CP_WAIT(1);
    __syncthreads();
    comp_slab(0);
    CP_WAIT(0);
    __syncthreads();
    comp_slab(1);

    const float* __restrict__ bias = ga.bias[z];
    __half* __restrict__ Ch = ga.Ch[z];

    if (Ch) {
        __syncthreads();
#pragma unroll
        for (int mt = 0; mt < 2; mt++) {
#pragma unroll
            for (int half_i = 0; half_i < 2; half_i++) {
#pragma unroll
                for (int ntg = 0; ntg < 2; ntg++) {
                    uint32_t h2[4];
#pragma unroll
                    for (int j = 0; j < 4; j++) {
                        int nt = ntg * 4 + j;
                        int gc = col0 + warp_n + nt * 8 + (lane & 3) * 2;
                        float2 b2 = *reinterpret_cast<const float2*>(bias + gc);
                        __half2 hv = __floats2half2_rn(
                            acc[mt][nt][half_i * 2 + 0] + b2.x,
                            acc[mt][nt][half_i * 2 + 1] + b2.y);
                        h2[j] = *reinterpret_cast<uint32_t*>(&hv);
                    }
                    int lr = warp_m + mt * 16 + half_i * 8 + (lane & 7);
                    int ch = (warp_n >> 3) + ntg * 4 + (lane >> 3);
                    uint32_t addr = sb + (uint32_t)(lr * 256)
                                  + (uint32_t)((ch ^ (lr & 7)) << 4);
                    stx4(addr, h2[0], h2[1], h2[2], h2[3]);
                }
            }
        }
        __syncthreads();
#pragma unroll
        for (int it = 0; it < 8; it++) {
            int id = tid + it * 256;
            int r = id >> 4, ch = id & 15;
            int gr = row0 + r;
            if (gr < M) {
                uint4 v = *reinterpret_cast<uint4*>(
                    smem + r * 256 + ((ch ^ (r & 7)) << 4));
                *reinterpret_cast<uint4*>(Ch + (size_t)gr * ldc + col0 + ch * 8) = v;
            }
        }
    } else {
        float*  __restrict__ Cf = ga.Cf[z];
        __half* __restrict__ Hout = ga.Hout[z];
#pragma unroll
        for (int mt = 0; mt < 2; mt++) {
            int gr0 = row0 + warp_m + mt * 16 + (lane >> 2);
#pragma unroll
            for (int nt = 0; nt < 8; nt++) {
                int gc = col0 + warp_n + nt * 8 + (lane & 3) * 2;
                float2 b2 = *reinterpret_cast<const float2*>(bias + gc);
#pragma unroll
                for (int half_i = 0; half_i < 2; half_i++) {
                    int gr = gr0 + half_i * 8;
                    if (gr >= M) continue;
                    float vx = acc[mt][nt][half_i * 2 + 0] + b2.x;
                    float vy = acc[mt][nt][half_i * 2 + 1] + b2.y;
                    *reinterpret_cast<float2*>(Cf + (size_t)gr * ldc + gc) =
                        make_float2(vx, vy);
                    if (Hout) {
                        *reinterpret_cast<__half2*>(Hout + (size_t)gr * DD + gc) =
                            __floats2half2_rn(vx, vy);
                    }
                }
            }
        }
    }
}

// ---------------------------------------------------------------------------
// Conversion / prep kernels
// ---------------------------------------------------------------------------
__global__ void split2_half_kernel(const float* __restrict__ x0,
                                   const float* __restrict__ x1,
                                   __half* __restrict__ h0,
                                   __half* __restrict__ h1)
{
    int i = blockIdx.x * blockDim.x + threadIdx.x;
    if (i >= 2 * NN * DD) return;
    if (i < NN * DD) h0[i] = __float2half(x0[i]);
    else             h1[i - NN * DD] = __float2half(x1[i - NN * DD]);
}

// One launch: K-major fat W fp16 + fat bias vectors + nw W fp16 (coalesced).
// CG regions use the interleaved Wf/Ws column layout (see header comment).
__global__ void prep_all_kernel(const float* __restrict__ gWl_b,
                                const float* __restrict__ gWr_b,
                                const float* __restrict__ gWl_r,
                                const float* __restrict__ gWr_r,
                                const float* __restrict__ cgL_Wf,
                                const float* __restrict__ cgL_Ws,
                                const float* __restrict__ cgR_Wf,
                                const float* __restrict__ cgR_Ws,
                                const float* __restrict__ cgL_bf,
                                const float* __restrict__ cgL_bs,
                                const float* __restrict__ cgR_bf,
                                const float* __restrict__ cgR_bs,
                                const float* __restrict__ nw_W,
                                __half* __restrict__ Wth_my,
                                __half* __restrict__ Wth_opp,
                                __half* __restrict__ nwWh,
                                float* __restrict__ bias_my,
                                float* __restrict__ bias_opp)
{
    int idx = blockIdx.x * blockDim.x + threadIdx.x;
    if (idx < DD * LDC) {
        int k = idx / LDC, n = idx % LDC;
        float wm, wo;
        if (n < 512) {
            wm = gWl_b[k * HD + n];               wo = gWr_b[k * HD + n];
        } else if (n < 1024) {
            int c = n - 512;
            wm = gWr_r[k * HD + c];               wo = gWl_r[k * HD + c];
        } else if (n < 1280) {
            int q = n - 1024;
            int c = (q >> 3) * 4 + (q & 3);
            const float* WL = (q & 4) ? cgL_Ws : cgL_Wf;
            wm = WL[(DD + k) * DD + c];           // my = src/bottom
            wo = WL[k * DD + c];                  // opp = dst/top
        } else {
            int q = n - 1280;
            int c = (q >> 3) * 4 + (q & 3);
            const float* WR = (q & 4) ? cgR_Ws : cgR_Wf;
            wm = WR[k * DD + c];                  // my = dst/top
            wo = WR[(DD + k) * DD + c];           // opp = src/bottom
        }
        Wth_my[idx]  = __float2half(wm);
        Wth_opp[idx] = __float2half(wo);
    }
    if (idx < DD * DD) {
        nwWh[idx] = __float2half(nw_W[idx]);   // already K-major
    }
    if (idx < LDC) {
        int n = idx;
        float bm = 0.f, bo = 0.f;
        if (n >= 1024 && n < 1280) {
            int q = n - 1024;
            int c = (q >> 3) * 4 + (q & 3);
            bo = (q & 4) ? cgL_bs[c] : cgL_bf[c];
        } else if (n >= 1280) {
            int q = n - 1280;
            int c = (q >> 3) * 4 + (q & 3);
            bm = (q & 4) ? cgR_bs[c] : cgR_bf[c];
        }
        bias_my[n] = bm;
        bias_opp[n] = bo;
    }
}

// ---------------------------------------------------------------------------
// CSR build (4 relations, built once per launch)
// ---------------------------------------------------------------------------
__global__ void csr_zero_kernel(int* __restrict__ cnt, int* __restrict__ fill)
{
    int i = blockIdx.x * blockDim.x + threadIdx.x;
    if (i < 4 * NN) { cnt[i] = 0; fill[i] = 0; }
}

__global__ void csr_hist_kernel(const int* __restrict__ d0,
                                const int* __restrict__ d1,
                                const int* __restrict__ d2,
                                const int* __restrict__ d3,
                                int* __restrict__ cnt)
{
    int i = blockIdx.x * blockDim.x + threadIdx.x;
    if (i >= EE) return;
    atomicAdd(&cnt[0 * NN + d0[i]], 1);
    atomicAdd(&cnt[1 * NN + d1[i]], 1);
    atomicAdd(&cnt[2 * NN + d2[i]], 1);
    atomicAdd(&cnt[3 * NN + d3[i]], 1);
}

__global__ void csr_scan_kernel(const int* __restrict__ cnt,
                                int* __restrict__ row)
{
    __shared__ int part[1024];
    const int rel = blockIdx.x;
    const int t = threadIdx.x;
    const int CH = (NN + 1023) / 1024;     // 20
    const int base = t * CH;
    int s = 0;
    for (int j = 0; j < CH; j++) {
        int i = base + j;
        if (i < NN) s += cnt[rel * NN + i];
    }
    part[t] = s;
    __syncthreads();
    for (int o = 1; o < 1024; o <<= 1) {
        int u = (t >= o) ? part[t - o] : 0;
        __syncthreads();
        part[t] += u;
        __syncthreads();
    }
    int run = part[t] - s;                 // exclusive prefix
    for (int j = 0; j < CH; j++) {
        int i = base + j;
        if (i < NN) {
            row[rel * (NN + 1) + i] = run;
            run += cnt[rel * NN + i];
        }
    }
    if (t == 1023) row[rel * (NN + 1) + NN] = part[1023];
}

__global__ void csr_scatter_kernel(const int* __restrict__ s0, const int* __restrict__ d0,
                                   const int* __restrict__ s1, const int* __restrict__ d1,
                                   const int* __restrict__ s2, const int* __restrict__ d2,
                                   const int* __restrict__ s3, const int* __restrict__ d3,
                                   const int* __restrict__ row,
                                   int* __restrict__ fill,
                                   int* __restrict__ srcs)
{
    int i = blockIdx.x * blockDim.x + threadIdx.x;
    if (i >= EE) return;
    {
        int d = d0[i];
        int pos = row[0 * (NN + 1) + d] + atomicAdd(&fill[0 * NN + d], 1);
        srcs[0 * EE + pos] = s0[i];
    }
    {
        int d = d1[i];
        int pos = row[1 * (NN + 1) + d] + atomicAdd(&fill[1 * NN + d], 1);
        srcs[1 * EE + pos] = s1[i];
    }
    {
        int d = d2[i];
        int pos = row[2 * (NN + 1) + d] + atomicAdd(&fill[2 * NN + d], 1);
        srcs[2 * EE + pos] = s2[i];
    }
    {
        int d = d3[i];
        int pos = row[3 * (NN + 1) + d] + atomicAdd(&fill[3 * NN + d], 1);
        srcs[3 * EE + pos] = s3[i];
    }
}

// ---------------------------------------------------------------------------
// Fused edge kernel: warp per dst node. Head-per-lane-group GAT + CG gate
// (interleaved layout: ONE uint4 per lane per edge), both loops pipelined.
// blockIdx.y = dst node type (0 = opp, 1 = my).
// ---------------------------------------------------------------------------
__device__ __forceinline__ float gate1(float f, float g)
{
    float sig = __fdividef(1.f, 1.f + __expf(-f));
    float sp  = fmaxf(g, 0.f) + __logf(1.f + __expf(-fabsf(g)));
    return sig * sp;
}

__global__ void __launch_bounds__(256)
edge_fused_kernel(EdgeArgs a)
{
    __shared__ float buf[8][HH][132];     // [warp][head][col], padded stride

    const int t = blockIdx.y;
    const int w = threadIdx.x >> 5;
    int d = blockIdx.x * 8 + w;
    int lane = threadIdx.x & 31;
    if (d >= NN) return;

    const int g  = lane >> 3;
    const int gl = lane & 7;
    const int cb = g * DD + gl * 16;

    float4 r4 = reinterpret_cast<const float4*>(a.xres[t] + (size_t)d * DD)[lane];
    float4 b4 = reinterpret_cast<const float4*>(a.bias[t])[lane];

    float4 o4;

    // ================= GAT phase (pipelined) =================
    {
        const __half* __restrict__ xl = a.xl[t];
        const int* __restrict__ row = a.growp[t];
        const int* __restrict__ srcs = a.gsrcs[t];

        float xr[16], at[16], acc[16];
        {
            const __half* xrp = a.xr[t] + (size_t)d * LDC + cb;
            half8_to_float8(*reinterpret_cast<const uint4*>(xrp),     xr);
            half8_to_float8(*reinterpret_cast<const uint4*>(xrp + 8), xr + 8);
            const float* ap = a.att[t] + cb;
#pragma unroll
            for (int k = 0; k < 4; k++) {
                float4 f = reinterpret_cast<const float4*>(ap)[k];
                at[k * 4 + 0] = f.x; at[k * 4 + 1] = f.y;
                at[k * 4 + 2] = f.z; at[k * 4 + 3] = f.w;
            }
#pragma unroll
            for (int j = 0; j < 16; j++) acc[j] = 0.f;
        }

        float s = 0.f;
        const int e0 = row[d], e1 = row[d + 1];

        uint4 c0, c1;
        if (e0 < e1) {
            int sn = srcs[e0];
            const __half* xlp = xl + (size_t)sn * LDC + cb;
            c0 = *reinterpret_cast<const uint4*>(xlp);
            c1 = *reinterpret_cast<const uint4*>(xlp + 8);
        }
        for (int p = e0; p < e1; p++) {
            uint4 d0 = c0, d1 = c1;
            if (p + 1 < e1) {
                int sn = srcs[p + 1];
                const __half* xlp = xl + (size_t)sn * LDC + cb;
                c0 = *reinterpret_cast<const uint4*>(xlp);
                c1 = *reinterpret_cast<const uint4*>(xlp + 8);
            }
            float l[16];
            half8_to_float8(d0, l);
            half8_to_float8(d1, l + 8);
            float part = 0.f;
#pragma unroll
            for (int j = 0; j < 16; j++) {
                float z = l[j] + xr[j];
                z = (z > 0.f) ? z : 0.2f * z;
                part = fmaf(z, at[j], part);
            }
            part += __shfl_xor_sync(0xffffffffu, part, 1);
            part += __shfl_xor_sync(0xffffffffu, part, 2);
            part += __shfl_xor_sync(0xffffffffu, part, 4);
            float e = __expf(part);
            s += e;
#pragma unroll
            for (int j = 0; j < 16; j++) acc[j] = fmaf(e, l[j], acc[j]);
        }

        float inv = 0.25f / (s + 1e-16f);
#pragma unroll
        for (int k = 0; k < 4; k++) {
            float4 v = make_float4(acc[k * 4 + 0] * inv, acc[k * 4 + 1] * inv,
                                   acc[k * 4 + 2] * inv, acc[k * 4 + 3] * inv);
            *reinterpret_cast<float4*>(&buf[w][g][gl * 16 + k * 4]) = v;
        }
        __syncwarp();

        o4 = make_float4(r4.x + b4.x, r4.y + b4.y, r4.z + b4.z, r4.w + b4.w);
#pragma unroll
        for (int gg = 0; gg < HH; gg++) {
            float4 v = *reinterpret_cast<const float4*>(&buf[w][gg][lane * 4]);
            o4.x += v.x; o4.y += v.y; o4.z += v.z; o4.w += v.w;
        }
        __syncwarp();
    }

    // ================= CG phase (interleaved; one uint4/lane/edge) ========
    {
        const __half* __restrict__ Ps = a.Ps[t];
        const int* __restrict__ row = a.crowp[t];
        const int* __restrict__ srcs = a.csrcs[t];

        // dst gate values: lane owns output cols 4*lane..4*lane+3 ->
        // interleaved halfs [8*lane, 8*lane+8) = f0..f3, s0..s3
        float dg[8];
        half8_to_float8(
            *reinterpret_cast<const uint4*>(a.Pd[t] + (size_t)d * LDC + lane * 8), dg);

        const int e0 = row[d], e1 = row[d + 1];

        uint4 cv;
        if (e0 < e1) {
            int sn = srcs[e0];
            cv = *reinterpret_cast<const uint4*>(Ps + (size_t)sn * LDC + lane * 8);
        }
        for (int p = e0; p < e1; p++) {
            uint4 dv = cv;
            if (p + 1 < e1) {
                int sn = srcs[p + 1];
                cv = *reinterpret_cast<const uint4*>(Ps + (size_t)sn * LDC + lane * 8);
            }
            float sg[8];
            half8_to_float8(dv, sg);
            o4.x += gate1(dg[0] + sg[0], dg[4] + sg[4]);
            o4.y += gate1(dg[1] + sg[1], dg[5] + sg[5]);
            o4.z += gate1(dg[2] + sg[2], dg[6] + sg[6]);
            o4.w += gate1(dg[3] + sg[3], dg[7] + sg[7]);
        }
    }

    size_t off = (size_t)d * DD + lane * 4;
    *reinterpret_cast<__half2*>(a.ah[t] + off)     = __floats2half2_rn(o4.x, o4.y);
    *reinterpret_cast<__half2*>(a.ah[t] + off + 2) = __floats2half2_rn(o4.z, o4.w);
}

// ---------------------------------------------------------------------------
// Host launcher
// ---------------------------------------------------------------------------
extern "C" void kernel_launch(void* const* d_in, const int* in_sizes, int n_in,
                              void* d_out, int out_size)
{
    const float* in_x_my  = (const float*)d_in[0];
    const float* in_x_opp = (const float*)d_in[1];
    const float* gWl_b = (const float*)d_in[2];
    const float* gWr_b = (const float*)d_in[3];
    const float* gatt_b = (const float*)d_in[4];
    const float* gb_b  = (const float*)d_in[5];
    const float* gWl_r = (const float*)d_in[6];
    const float* gWr_r = (const float*)d_in[7];
    const float* gatt_r = (const float*)d_in[8];
    const float* gb_r  = (const float*)d_in[9];
    const float* cgL_Wf = (const float*)d_in[10];
    const float* cgL_bf = (const float*)d_in[11];
    const float* cgL_Ws = (const float*)d_in[12];
    const float* cgL_bs = (const float*)d_in[13];
    const float* cgR_Wf = (const float*)d_in[14];
    const float* cgR_bf = (const float*)d_in[15];
    const float* cgR_Ws = (const float*)d_in[16];
    const float* cgR_bs = (const float*)d_in[17];
    const float* nw_W = (const float*)d_in[18];
    const float* nw_b = (const float*)d_in[19];
    const int* ei_beats     = (const int*)d_in[20];
    const int* ei_loses     = (const int*)d_in[21];
    const int* ei_rev_beats = (const int*)d_in[22];
    const int* ei_rev_loses = (const int*)d_in[23];

    float* out = (float*)d_out;

    float *x_my, *x_opp, *bias_b, *bias_ob;
    __half *C_my, *C_opp;
    __half *xh_my, *xh_opp, *ah_my, *ah_opp;
    __half *Wth_mb, *Wth_ob, *nwWhb;
    int *rowp, *cntp, *fillp, *srcsp;
    cudaGetSymbolAddress((void**)&C_my,  g_C_my);
    cudaGetSymbolAddress((void**)&C_opp, g_C_opp);
    cudaGetSymbolAddress((void**)&x_my,  g_x_my);
    cudaGetSymbolAddress((void**)&x_opp, g_x_opp);
    cudaGetSymbolAddress((void**)&bias_b,  g_bias_my);
    cudaGetSymbolAddress((void**)&bias_ob, g_bias_opp);
    cudaGetSymbolAddress((void**)&xh_my,  g_xh_my);
    cudaGetSymbolAddress((void**)&xh_opp, g_xh_opp);
    cudaGetSymbolAddress((void**)&ah_my,  g_ah_my);
    cudaGetSymbolAddress((void**)&ah_opp, g_ah_opp);
    cudaGetSymbolAddress((void**)&Wth_mb,  g_Wth_my);
    cudaGetSymbolAddress((void**)&Wth_ob, g_Wth_opp);
    cudaGetSymbolAddress((void**)&nwWhb, g_nwWh);
    cudaGetSymbolAddress((void**)&rowp,  g_row);
    cudaGetSymbolAddress((void**)&cntp,  g_cnt);
    cudaGetSymbolAddress((void**)&fillp, g_fill);
    cudaGetSymbolAddress((void**)&srcsp, g_srcs);

    cudaFuncSetAttribute(mma_gemm, cudaFuncAttributeMaxDynamicSharedMemorySize,
                         DYN_SMEM);

    // side stream + events (created once, outside any capture)
    static cudaStream_t s2 = nullptr;
    static cudaEvent_t evFork = nullptr, evPrep0 = nullptr, evCsr = nullptr,
                       evPrep1 = nullptr;
    if (!s2) {
        cudaStreamCreateWithFlags(&s2, cudaStreamNonBlocking);
        cudaEventCreateWithFlags(&evFork,  cudaEventDisableTiming);
        cudaEventCreateWithFlags(&evPrep0, cudaEventDisableTiming);
        cudaEventCreateWithFlags(&evCsr,   cudaEventDisableTiming);
        cudaEventCreateWithFlags(&evPrep1, cudaEventDisableTiming);
    }

    const int* src_b  = ei_beats;      const int* dst_b  = ei_beats + EE;
    const int* src_l  = ei_loses;      const int* dst_l  = ei_loses + EE;
    const int* src_rb = ei_rev_beats;  const int* dst_rb = ei_rev_beats + EE;
    const int* src_rl = ei_rev_loses;  const int* dst_rl = ei_rev_loses + EE;

    const int node_blocks = (NN + 7) / 8;
    const int e_blocks    = (EE + 255) / 256;
    const int mtiles      = (NN + 127) / 128;      // 157

    __half* Wth_my_l[2]  = { Wth_mb,  Wth_mb + DD * LDC };
    __half* Wth_opp_l[2] = { Wth_ob,  Wth_ob + DD * LDC };
    __half* nwWh_l[2]    = { nwWhb,   nwWhb + DD * DD };
    float*  bias_my_l[2] = { bias_b,  bias_b + LDC };
    float*  bias_opp_l[2]= { bias_ob, bias_ob + LDC };

    // ---- fork side stream ----
    cudaEventRecord(evFork, 0);
    cudaStreamWaitEvent(s2, evFork, 0);

    // side stream: layer-0 prep, CSR build, layer-1 prep
    prep_all_kernel<<<(DD * LDC + 255) / 256, 256, 0, s2>>>(
        gWl_b, gWr_b, gWl_r, gWr_r,
        cgL_Wf, cgL_Ws, cgR_Wf, cgR_Ws,
        cgL_bf, cgL_bs, cgR_bf, cgR_bs,
        nw_W,
        Wth_my_l[0], Wth_opp_l[0], nwWh_l[0],
        bias_my_l[0], bias_opp_l[0]);
    cudaEventRecord(evPrep0, s2);
    csr_zero_kernel<<<(4 * NN + 255) / 256, 256, 0, s2>>>(cntp, fillp);
    csr_hist_kernel<<<e_blocks, 256, 0, s2>>>(dst_b, dst_rl, dst_l, dst_rb, cntp);
    csr_scan_kernel<<<4, 1024, 0, s2>>>(cntp, rowp);
    csr_scatter_kernel<<<e_blocks, 256, 0, s2>>>(src_b, dst_b, src_rl, dst_rl,
                                                 src_l, dst_l, src_rb, dst_rb,
                                                 rowp, fillp, srcsp);
    cudaEventRecord(evCsr, s2);
    {
        const size_t oW = (size_t)1 * DD * HD;
        const size_t oB = (size_t)1 * DD;
        const size_t oC = (size_t)1 * 2 * DD * DD;
        const size_t oN = (size_t)1 * DD * DD;
        prep_all_kernel<<<(DD * LDC + 255) / 256, 256, 0, s2>>>(
            gWl_b + oW, gWr_b + oW, gWl_r + oW, gWr_r + oW,
            cgL_Wf + oC, cgL_Ws + oC, cgR_Wf + oC, cgR_Ws + oC,
            cgL_bf + oB, cgL_bs + oB, cgR_bf + oB, cgR_bs + oB,
            nw_W + oN,
            Wth_my_l[1], Wth_opp_l[1], nwWh_l[1],
            bias_my_l[1], bias_opp_l[1]);
    }
    cudaEventRecord(evPrep1, s2);

    // main stream: input splits
    split2_half_kernel<<<(2 * NN * DD + 255) / 256, 256>>>(
        in_x_my, in_x_opp, xh_my, xh_opp);
    cudaStreamWaitEvent(0, evPrep0, 0);

    const float* cur_my  = in_x_my;
    const float* cur_opp = in_x_opp;

    for (int l = 0; l < LLAYERS; l++) {
        const size_t oA = (size_t)l * HH * DD;
        const size_t oB = (size_t)l * DD;

        if (l > 0) cudaStreamWaitEvent(0, evPrep1, 0);

        // ---- fat projection GEMMs ----
        {
            GemmArgs ga;
            ga.Ah[0] = xh_my;   ga.Ah[1] = xh_opp;
            ga.Bh[0] = Wth_my_l[l];  ga.Bh[1] = Wth_opp_l[l];
            ga.bias[0] = bias_my_l[l];  ga.bias[1] = bias_opp_l[l];
            ga.Ch[0] = C_my;    ga.Ch[1] = C_opp;
            ga.Cf[0] = nullptr; ga.Cf[1] = nullptr;
            ga.Hout[0] = nullptr; ga.Hout[1] = nullptr;
            ga.M = NN; ga.ldc = LDC; ga.ldb = LDC;
            dim3 grid(LDC / 128, mtiles, 2);
            mma_gemm<<<grid, 256, DYN_SMEM>>>(ga);
        }

        if (l == 0) cudaStreamWaitEvent(0, evCsr, 0);

        // ---- fused edge phase: GAT + CG per dst type, one launch ----
        {
            EdgeArgs a;
            // t=0: dst opp — GAT beats (rel 0), CG lose interleaved (rel 2)
            a.xl[0] = C_my;        a.xr[0] = C_opp;
            a.att[0] = gatt_b + oA;
            a.growp[0] = rowp + 0 * (NN + 1);  a.gsrcs[0] = srcsp + 0 * EE;
            a.Pd[0] = C_opp + 1024; a.Ps[0] = C_my + 1024;
            a.crowp[0] = rowp + 2 * (NN + 1);  a.csrcs[0] = srcsp + 2 * EE;
            a.xres[0] = cur_opp;   a.bias[0] = gb_b + oB;  a.ah[0] = ah_opp;
            // t=1: dst my — GAT rev_loses (rel 1), CG rev interleaved (rel 3)
            a.xl[1] = C_opp + 512; a.xr[1] = C_my + 512;
            a.att[1] = gatt_r + oA;
            a.growp[1] = rowp + 1 * (NN + 1);  a.gsrcs[1] = srcsp + 1 * EE;
            a.Pd[1] = C_my + 1280; a.Ps[1] = C_opp + 1280;
            a.crowp[1] = rowp + 3 * (NN + 1);  a.csrcs[1] = srcsp + 3 * EE;
            a.xres[1] = cur_my;    a.bias[1] = gb_r + oB;  a.ah[1] = ah_my;
            dim3 grid(node_blocks, 2);
            edge_fused_kernel<<<grid, 256>>>(a);
        }

        // ---- nodewise Linear (both node types, one launch; fp32 out) ----
        {
            float* out_my  = (l == LLAYERS - 1) ? out           : x_my;
            float* out_opp = (l == LLAYERS - 1) ? out + NN * DD : x_opp;
            bool last = (l == LLAYERS - 1);
            GemmArgs ga;
            ga.Ah[0] = ah_my;   ga.Ah[1] = ah_opp;
            ga.Bh[0] = nwWh_l[l];  ga.Bh[1] = nwWh_l[l];
            ga.bias[0] = nw_b + oB;  ga.bias[1] = nw_b + oB;
            ga.Ch[0] = nullptr; ga.Ch[1] = nullptr;
            ga.Cf[0] = out_my;  ga.Cf[1] = out_opp;
            ga.Hout[0] = last ? nullptr : xh_my;
            ga.Hout[1] = last ? nullptr : xh_opp;
            ga.M = NN; ga.ldc = DD; ga.ldb = DD;
            dim3 grid(1, mtiles, 2);
            mma_gemm<<<grid, 256, DYN_SMEM>>>(ga);
        }

        cur_my  = x_my;
        cur_opp = x_opp;
    }
}

// round 17
// speedup vs baseline: 1.0328x; 1.0328x over previous
#include <cuda_runtime.h>
#include <cuda_fp16.h>
#include <math.h>
#include <stdint.h>

// ---------------------------------------------------------------------------
// Problem constants
// ---------------------------------------------------------------------------
#define NN 20000
#define DD 128
#define HH 4
#define EE 80000
#define LLAYERS 2
#define HD (HH * DD)      // 512
#define LDC 1536          // fat projection width per node type

// Fat column layout (per node type X in {my, opp}):
//  [0,512)      GAT projection #1 (my: Wl_beats ; opp: Wr_beats)
//  [512,1024)   GAT projection #2 (my: Wr_rev   ; opp: Wl_rev)
//  [1024,1280)  CG lose, INTERLEAVED: group k (k=0..31) = 8 cols:
//               cols 1024+8k+{0..3} = Wf cols {4k..4k+3},
//               cols 1024+8k+{4..7} = Ws cols {4k..4k+3}
//               (my: src/bottom rows ; opp: dst/top rows + biases)
//  [1280,1536)  CG rev, same interleave (my: dst/top + biases ; opp: src/bottom)

// ---------------------------------------------------------------------------
// Static device scratch
// ---------------------------------------------------------------------------
__device__ __align__(16) __half g_C_my [(size_t)NN * LDC];   // fp16 fat features
__device__ __align__(16) __half g_C_opp[(size_t)NN * LDC];

__device__ __align__(16) float g_x_my [NN * DD];
__device__ __align__(16) float g_x_opp[NN * DD];

// fp16 feature operands (A side of GEMMs)
__device__ __align__(16) __half g_xh_my [NN * DD];
__device__ __align__(16) __half g_xh_opp[NN * DD];
__device__ __align__(16) __half g_ah_my [NN * DD];
__device__ __align__(16) __half g_ah_opp[NN * DD];

// fp16 weight operands (B side), K-MAJOR, DOUBLE-BUFFERED per layer
__device__ __align__(16) __half g_Wth_my [2][DD * LDC];
__device__ __align__(16) __half g_Wth_opp[2][DD * LDC];
__device__ __align__(16) __half g_nwWh   [2][DD * DD];
__device__ __align__(16) float g_bias_my [2][LDC];
__device__ __align__(16) float g_bias_opp[2][LDC];

// CSR (4 relations: 0=beats, 1=rev_loses, 2=loses, 3=rev_beats), built once
__device__ int g_row [4 * (NN + 1)];
__device__ int g_cnt [4 * NN];
__device__ int g_fill[4 * NN];
__device__ int g_srcs[4 * EE];

// ---------------------------------------------------------------------------
// Arg structs for merged launches
// ---------------------------------------------------------------------------
struct GemmArgs {
    const __half *Ah[2], *Bh[2];
    const float *bias[2];
    __half *Ch[2];     // fp16 C output (fat projections) -> stmatrix epilogue
    float  *Cf[2];     // fp32 C output (nodewise Linear) -> direct epilogue
    __half *Hout[2];   // fp16 feature copy (next-layer A)
    int M, ldc, ldb;
};

// Fused edge args: index = dst node type (0 = opp, 1 = my)
struct EdgeArgs {
    const __half *xl[2], *xr[2];
    const float *att[2];
    const int *growp[2], *gsrcs[2];
    const __half *Pd[2], *Ps[2];       // interleaved CG gate bases (dst, src)
    const int *crowp[2], *csrcs[2];
    const float *xres[2], *bias[2];
    __half *ah[2];
};

// ---------------------------------------------------------------------------
// Warp MMA / cp.async helpers
// ---------------------------------------------------------------------------
__device__ __forceinline__ uint32_t smem_to_u32(const void* p)
{
    uint32_t a;
    asm("{ .reg .u64 t; cvta.to.shared.u64 t, %1; cvt.u32.u64 %0, t; }"
        : "=r"(a) : "l"(p));
    return a;
}

__device__ __forceinline__ void ldx4(uint32_t* r, uint32_t addr)
{
    asm volatile("ldmatrix.sync.aligned.m8n8.x4.shared.b16 {%0,%1,%2,%3}, [%4];"
                 : "=r"(r[0]), "=r"(r[1]), "=r"(r[2]), "=r"(r[3]) : "r"(addr));
}

__device__ __forceinline__ void ldx4t(uint32_t* r, uint32_t addr)
{
    asm volatile("ldmatrix.sync.aligned.m8n8.x4.trans.shared.b16 {%0,%1,%2,%3}, [%4];"
                 : "=r"(r[0]), "=r"(r[1]), "=r"(r[2]), "=r"(r[3]) : "r"(addr));
}

__device__ __forceinline__ void stx4(uint32_t addr, uint32_t r0, uint32_t r1,
                                     uint32_t r2, uint32_t r3)
{
    asm volatile("stmatrix.sync.aligned.m8n8.x4.shared.b16 [%0], {%1,%2,%3,%4};"
                 :: "r"(addr), "r"(r0), "r"(r1), "r"(r2), "r"(r3) : "memory");
}

__device__ __forceinline__ void mma16816(float* c, const uint32_t* a,
                                         uint32_t b0, uint32_t b1)
{
    asm volatile(
        "mma.sync.aligned.m16n8k16.row.col.f32.f16.f16.f32 "
        "{%0,%1,%2,%3}, {%4,%5,%6,%7}, {%8,%9}, {%0,%1,%2,%3};"
        : "+f"(c[0]), "+f"(c[1]), "+f"(c[2]), "+f"(c[3])
        : "r"(a[0]), "r"(a[1]), "r"(a[2]), "r"(a[3]), "r"(b0), "r"(b1));
}

__device__ __forceinline__ void cpa16(uint32_t dst, const void* src, int sz)
{
    asm volatile("cp.async.cg.shared.global [%0], [%1], 16, %2;"
                 :: "r"(dst), "l"(src), "r"(sz));
}
#define CP_COMMIT() asm volatile("cp.async.commit_group;" ::: "memory")
#define CP_WAIT(n)  asm volatile("cp.async.wait_group %0;" :: "n"(n) : "memory")

__device__ __forceinline__ float4 half4_to_float4(uint2 v)
{
    __half2 h01 = *reinterpret_cast<__half2*>(&v.x);
    __half2 h23 = *reinterpret_cast<__half2*>(&v.y);
    float2 f0 = __half22float2(h01);
    float2 f1 = __half22float2(h23);
    return make_float4(f0.x, f0.y, f1.x, f1.y);
}

__device__ __forceinline__ void half8_to_float8(uint4 v, float* f)
{
    float4 a = half4_to_float4(make_uint2(v.x, v.y));
    float4 b = half4_to_float4(make_uint2(v.z, v.w));
    f[0] = a.x; f[1] = a.y; f[2] = a.z; f[3] = a.w;
    f[4] = b.x; f[5] = b.y; f[6] = b.z; f[7] = b.w;
}

// ---------------------------------------------------------------------------
// Tensor-core GEMM: C[M, col0..+128] = A[M,128] @ B[128, Nc] + bias.
// A row-major fp16; B K-MAJOR fp16 (ldb cols), loaded via ldmatrix.trans.
// BK=32 slabs, 2-stage cp.async ring, 32 KB smem.
// Ch path: stmatrix -> smem -> coalesced 128B stores.
// ---------------------------------------------------------------------------
#define SM_A  0
#define SM_B  8192
#define STAGE_BYTES 16384
#define DYN_SMEM 32768

__global__ void __launch_bounds__(256, 2)
mma_gemm(GemmArgs ga)
{
    extern __shared__ char smem[];
    const uint32_t sb = smem_to_u32(smem);

    const int z = blockIdx.z;
    const __half* __restrict__ Ah = ga.Ah[z];
    const __half* __restrict__ Bh = ga.Bh[z];
    const int M = ga.M, ldc = ga.ldc, ldb = ga.ldb;

    const int tid  = threadIdx.x;
    const int wid  = tid >> 5;
    const int lane = tid & 31;
    const int row0 = blockIdx.y * 128;
    const int col0 = blockIdx.x * 128;

    const int warp_m = (wid & 3) * 32;
    const int warp_n = (wid >> 2) * 64;

    float acc[2][8][4];
#pragma unroll
    for (int mt = 0; mt < 2; mt++)
#pragma unroll
        for (int nt = 0; nt < 8; nt++)
#pragma unroll
            for (int j = 0; j < 4; j++) acc[mt][nt][j] = 0.f;

    auto load_slab = [&](int slab, int buf) {
        const uint32_t bufb = sb + buf * STAGE_BYTES;
        const int kbase = slab * 32;
#pragma unroll
        for (int it = 0; it < 2; it++) {
            int c  = tid + it * 256;
            int r  = c >> 2;
            int ch = c & 3;
            uint32_t so = (uint32_t)r * 64 + (uint32_t)((ch ^ ((r >> 1) & 3)) * 16);
            int kc = kbase + ch * 8;
            int gr = row0 + r;
            int asz = (gr < M) ? 16 : 0;
            int gra = (gr < M) ? gr : 0;
            cpa16(bufb + SM_A + so, Ah + (size_t)gra * DD + kc, asz);
        }
#pragma unroll
        for (int it = 0; it < 2; it++) {
            int c  = tid + it * 256;
            int kr = c >> 4;
            int ch = c & 15;
            uint32_t so = (uint32_t)kr * 256 + (uint32_t)((ch ^ (kr & 7)) * 16);
            cpa16(bufb + SM_B + so,
                  Bh + (size_t)(kbase + kr) * ldb + col0 + ch * 8, 16);
        }
        CP_COMMIT();
    };

    auto comp_slab = [&](int buf) {
        const uint32_t bufb = sb + buf * STAGE_BYTES;
#pragma unroll
        for (int ks = 0; ks < 2; ks++) {
            uint32_t af[2][4];
#pragma unroll
            for (int mt = 0; mt < 2; mt++) {
                int r  = warp_m + mt * 16 + (lane & 7) + ((lane >> 3) & 1) * 8;
                int ch = ks * 2 + (lane >> 4);
                uint32_t off = (uint32_t)r * 64
                             + (uint32_t)((ch ^ ((r >> 1) & 3)) * 16);
                ldx4(af[mt], bufb + SM_A + off);
            }
            uint32_t bf[4][4];
#pragma unroll
            for (int np = 0; np < 4; np++) {
                int kr = ks * 16 + (lane & 7) + ((lane >> 3) & 1) * 8;
                int ch = (warp_n >> 3) + np * 2 + ((lane >> 4) & 1);
                uint32_t off = (uint32_t)kr * 256
                             + (uint32_t)((ch ^ (kr & 7)) * 16);
                ldx4t(bf[np], bufb + SM_B + off);
            }
#pragma unroll
            for (int mt = 0; mt < 2; mt++) {
#pragma unroll
                for (int nt = 0; nt < 8; nt++) {
                    int np = nt >> 1, hi = (nt & 1) * 2;
                    mma16816(acc[mt][nt], af[mt], bf[np][hi], bf[np][hi + 1]);
                }
            }
        }
    };

    load_slab(0, 0);
    load_slab(1, 1);
    CP_WAIT(1);
    __syncthreads();
    comp_slab(0);
    __syncthreads();
    load_slab(2, 0);
    CP_WAIT(1);
    __syncthreads();
    comp_slab(1);
    __syncthreads();
    load_slab(3, 1);
    CP_WAIT(1);
    __syncthreads();
    comp_slab(0);
    CP_WAIT(0);
    __syncthreads();
    comp_slab(1);

    const float* __restrict__ bias = ga.bias[z];
    __half* __restrict__ Ch = ga.Ch[z];

    if (Ch) {
        __syncthreads();
#pragma unroll
        for (int mt = 0; mt < 2; mt++) {
#pragma unroll
            for (int half_i = 0; half_i < 2; half_i++) {
#pragma unroll
                for (int ntg = 0; ntg < 2; ntg++) {
                    uint32_t h2[4];
#pragma unroll
                    for (int j = 0; j < 4; j++) {
                        int nt = ntg * 4 + j;
                        int gc = col0 + warp_n + nt * 8 + (lane & 3) * 2;
                        float2 b2 = *reinterpret_cast<const float2*>(bias + gc);
                        __half2 hv = __floats2half2_rn(
                            acc[mt][nt][half_i * 2 + 0] + b2.x,
                            acc[mt][nt][half_i * 2 + 1] + b2.y);
                        h2[j] = *reinterpret_cast<uint32_t*>(&hv);
                    }
                    int lr = warp_m + mt * 16 + half_i * 8 + (lane & 7);
                    int ch = (warp_n >> 3) + ntg * 4 + (lane >> 3);
                    uint32_t addr = sb + (uint32_t)(lr * 256)
                                  + (uint32_t)((ch ^ (lr & 7)) << 4);
                    stx4(addr, h2[0], h2[1], h2[2], h2[3]);
                }
            }
        }
        __syncthreads();
#pragma unroll
        for (int it = 0; it < 8; it++) {
            int id = tid + it * 256;
            int r = id >> 4, ch = id & 15;
            int gr = row0 + r;
            if (gr < M) {
                uint4 v = *reinterpret_cast<uint4*>(
                    smem + r * 256 + ((ch ^ (r & 7)) << 4));
                *reinterpret_cast<uint4*>(Ch + (size_t)gr * ldc + col0 + ch * 8) = v;
            }
        }
    } else {
        float*  __restrict__ Cf = ga.Cf[z];
        __half* __restrict__ Hout = ga.Hout[z];
#pragma unroll
        for (int mt = 0; mt < 2; mt++) {
            int gr0 = row0 + warp_m + mt * 16 + (lane >> 2);
#pragma unroll
            for (int nt = 0; nt < 8; nt++) {
                int gc = col0 + warp_n + nt * 8 + (lane & 3) * 2;
                float2 b2 = *reinterpret_cast<const float2*>(bias + gc);
#pragma unroll
                for (int half_i = 0; half_i < 2; half_i++) {
                    int gr = gr0 + half_i * 8;
                    if (gr >= M) continue;
                    float vx = acc[mt][nt][half_i * 2 + 0] + b2.x;
                    float vy = acc[mt][nt][half_i * 2 + 1] + b2.y;
                    *reinterpret_cast<float2*>(Cf + (size_t)gr * ldc + gc) =
                        make_float2(vx, vy);
                    if (Hout) {
                        *reinterpret_cast<__half2*>(Hout + (size_t)gr * DD + gc) =
                            __floats2half2_rn(vx, vy);
                    }
                }
            }
        }
    }
}

// ---------------------------------------------------------------------------
// Conversion / prep kernels
// ---------------------------------------------------------------------------
__global__ void split2_half_kernel(const float* __restrict__ x0,
                                   const float* __restrict__ x1,
                                   __half* __restrict__ h0,
                                   __half* __restrict__ h1)
{
    int i = blockIdx.x * blockDim.x + threadIdx.x;
    if (i >= 2 * NN * DD) return;
    if (i < NN * DD) h0[i] = __float2half(x0[i]);
    else             h1[i - NN * DD] = __float2half(x1[i - NN * DD]);
}

// One launch: K-major fat W fp16 + fat bias vectors + nw W fp16 (coalesced).
// CG regions use the interleaved Wf/Ws column layout (see header comment).
__global__ void prep_all_kernel(const float* __restrict__ gWl_b,
                                const float* __restrict__ gWr_b,
                                const float* __restrict__ gWl_r,
                                const float* __restrict__ gWr_r,
                                const float* __restrict__ cgL_Wf,
                                const float* __restrict__ cgL_Ws,
                                const float* __restrict__ cgR_Wf,
                                const float* __restrict__ cgR_Ws,
                                const float* __restrict__ cgL_bf,
                                const float* __restrict__ cgL_bs,
                                const float* __restrict__ cgR_bf,
                                const float* __restrict__ cgR_bs,
                                const float* __restrict__ nw_W,
                                __half* __restrict__ Wth_my,
                                __half* __restrict__ Wth_opp,
                                __half* __restrict__ nwWh,
                                float* __restrict__ bias_my,
                                float* __restrict__ bias_opp)
{
    int idx = blockIdx.x * blockDim.x + threadIdx.x;
    if (idx < DD * LDC) {
        int k = idx / LDC, n = idx % LDC;
        float wm, wo;
        if (n < 512) {
            wm = gWl_b[k * HD + n];               wo = gWr_b[k * HD + n];
        } else if (n < 1024) {
            int c = n - 512;
            wm = gWr_r[k * HD + c];               wo = gWl_r[k * HD + c];
        } else if (n < 1280) {
            int q = n - 1024;
            int c = (q >> 3) * 4 + (q & 3);
            const float* WL = (q & 4) ? cgL_Ws : cgL_Wf;
            wm = WL[(DD + k) * DD + c];           // my = src/bottom
            wo = WL[k * DD + c];                  // opp = dst/top
        } else {
            int q = n - 1280;
            int c = (q >> 3) * 4 + (q & 3);
            const float* WR = (q & 4) ? cgR_Ws : cgR_Wf;
            wm = WR[k * DD + c];                  // my = dst/top
            wo = WR[(DD + k) * DD + c];           // opp = src/bottom
        }
        Wth_my[idx]  = __float2half(wm);
        Wth_opp[idx] = __float2half(wo);
    }
    if (idx < DD * DD) {
        nwWh[idx] = __float2half(nw_W[idx]);   // already K-major
    }
    if (idx < LDC) {
        int n = idx;
        float bm = 0.f, bo = 0.f;
        if (n >= 1024 && n < 1280) {
            int q = n - 1024;
            int c = (q >> 3) * 4 + (q & 3);
            bo = (q & 4) ? cgL_bs[c] : cgL_bf[c];
        } else if (n >= 1280) {
            int q = n - 1280;
            int c = (q >> 3) * 4 + (q & 3);
            bm = (q & 4) ? cgR_bs[c] : cgR_bf[c];
        }
        bias_my[n] = bm;
        bias_opp[n] = bo;
    }
}

// ---------------------------------------------------------------------------
// CSR build (4 relations, built once per launch)
// ---------------------------------------------------------------------------
__global__ void csr_zero_kernel(int* __restrict__ cnt, int* __restrict__ fill)
{
    int i = blockIdx.x * blockDim.x + threadIdx.x;
    if (i < 4 * NN) { cnt[i] = 0; fill[i] = 0; }
}

__global__ void csr_hist_kernel(const int* __restrict__ d0,
                                const int* __restrict__ d1,
                                const int* __restrict__ d2,
                                const int* __restrict__ d3,
                                int* __restrict__ cnt)
{
    int i = blockIdx.x * blockDim.x + threadIdx.x;
    if (i >= EE) return;
    atomicAdd(&cnt[0 * NN + d0[i]], 1);
    atomicAdd(&cnt[1 * NN + d1[i]], 1);
    atomicAdd(&cnt[2 * NN + d2[i]], 1);
    atomicAdd(&cnt[3 * NN + d3[i]], 1);
}

__global__ void csr_scan_kernel(const int* __restrict__ cnt,
                                int* __restrict__ row)
{
    __shared__ int part[1024];
    const int rel = blockIdx.x;
    const int t = threadIdx.x;
    const int CH = (NN + 1023) / 1024;     // 20
    const int base = t * CH;
    int s = 0;
    for (int j = 0; j < CH; j++) {
        int i = base + j;
        if (i < NN) s += cnt[rel * NN + i];
    }
    part[t] = s;
    __syncthreads();
    for (int o = 1; o < 1024; o <<= 1) {
        int u = (t >= o) ? part[t - o] : 0;
        __syncthreads();
        part[t] += u;
        __syncthreads();
    }
    int run = part[t] - s;                 // exclusive prefix
    for (int j = 0; j < CH; j++) {
        int i = base + j;
        if (i < NN) {
            row[rel * (NN + 1) + i] = run;
            run += cnt[rel * NN + i];
        }
    }
    if (t == 1023) row[rel * (NN + 1) + NN] = part[1023];
}

__global__ void csr_scatter_kernel(const int* __restrict__ s0, const int* __restrict__ d0,
                                   const int* __restrict__ s1, const int* __restrict__ d1,
                                   const int* __restrict__ s2, const int* __restrict__ d2,
                                   const int* __restrict__ s3, const int* __restrict__ d3,
                                   const int* __restrict__ row,
                                   int* __restrict__ fill,
                                   int* __restrict__ srcs)
{
    int i = blockIdx.x * blockDim.x + threadIdx.x;
    if (i >= EE) return;
    {
        int d = d0[i];
        int pos = row[0 * (NN + 1) + d] + atomicAdd(&fill[0 * NN + d], 1);
        srcs[0 * EE + pos] = s0[i];
    }
    {
        int d = d1[i];
        int pos = row[1 * (NN + 1) + d] + atomicAdd(&fill[1 * NN + d], 1);
        srcs[1 * EE + pos] = s1[i];
    }
    {
        int d = d2[i];
        int pos = row[2 * (NN + 1) + d] + atomicAdd(&fill[2 * NN + d], 1);
        srcs[2 * EE + pos] = s2[i];
    }
    {
        int d = d3[i];
        int pos = row[3 * (NN + 1) + d] + atomicAdd(&fill[3 * NN + d], 1);
        srcs[3 * EE + pos] = s3[i];
    }
}

// ---------------------------------------------------------------------------
// Fused edge kernel: warp per dst node. Head-per-lane-group GAT + CG gate
// (interleaved layout: ONE uint4 per lane per edge), both loops pipelined.
// blockIdx.y = dst node type (0 = opp, 1 = my).
// ---------------------------------------------------------------------------
__device__ __forceinline__ float gate1(float f, float g)
{
    float sig = __fdividef(1.f, 1.f + __expf(-f));
    float sp  = fmaxf(g, 0.f) + __logf(1.f + __expf(-fabsf(g)));
    return sig * sp;
}

__global__ void __launch_bounds__(256)
edge_fused_kernel(EdgeArgs a)
{
    __shared__ float buf[8][HH][132];     // [warp][head][col], padded stride

    const int t = blockIdx.y;
    const int w = threadIdx.x >> 5;
    int d = blockIdx.x * 8 + w;
    int lane = threadIdx.x & 31;
    if (d >= NN) return;

    const int g  = lane >> 3;
    const int gl = lane & 7;
    const int cb = g * DD + gl * 16;

    float4 r4 = reinterpret_cast<const float4*>(a.xres[t] + (size_t)d * DD)[lane];
    float4 b4 = reinterpret_cast<const float4*>(a.bias[t])[lane];

    float4 o4;

    // ================= GAT phase (pipelined) =================
    {
        const __half* __restrict__ xl = a.xl[t];
        const int* __restrict__ row = a.growp[t];
        const int* __restrict__ srcs = a.gsrcs[t];

        float xr[16], at[16], acc[16];
        {
            const __half* xrp = a.xr[t] + (size_t)d * LDC + cb;
            half8_to_float8(*reinterpret_cast<const uint4*>(xrp),     xr);
            half8_to_float8(*reinterpret_cast<const uint4*>(xrp + 8), xr + 8);
            const float* ap = a.att[t] + cb;
#pragma unroll
            for (int k = 0; k < 4; k++) {
                float4 f = reinterpret_cast<const float4*>(ap)[k];
                at[k * 4 + 0] = f.x; at[k * 4 + 1] = f.y;
                at[k * 4 + 2] = f.z; at[k * 4 + 3] = f.w;
            }
#pragma unroll
            for (int j = 0; j < 16; j++) acc[j] = 0.f;
        }

        float s = 0.f;
        const int e0 = row[d], e1 = row[d + 1];

        uint4 c0, c1;
        if (e0 < e1) {
            int sn = srcs[e0];
            const __half* xlp = xl + (size_t)sn * LDC + cb;
            c0 = *reinterpret_cast<const uint4*>(xlp);
            c1 = *reinterpret_cast<const uint4*>(xlp + 8);
        }
        for (int p = e0; p < e1; p++) {
            uint4 d0 = c0, d1 = c1;
            if (p + 1 < e1) {
                int sn = srcs[p + 1];
                const __half* xlp = xl + (size_t)sn * LDC + cb;
                c0 = *reinterpret_cast<const uint4*>(xlp);
                c1 = *reinterpret_cast<const uint4*>(xlp + 8);
            }
            float l[16];
            half8_to_float8(d0, l);
            half8_to_float8(d1, l + 8);
            float part = 0.f;
#pragma unroll
            for (int j = 0; j < 16; j++) {
                float z = l[j] + xr[j];
                z = (z > 0.f) ? z : 0.2f * z;
                part = fmaf(z, at[j], part);
            }
            part += __shfl_xor_sync(0xffffffffu, part, 1);
            part += __shfl_xor_sync(0xffffffffu, part, 2);
            part += __shfl_xor_sync(0xffffffffu, part, 4);
            float e = __expf(part);
            s += e;
#pragma unroll
            for (int j = 0; j < 16; j++) acc[j] = fmaf(e, l[j], acc[j]);
        }

        float inv = 0.25f / (s + 1e-16f);
#pragma unroll
        for (int k = 0; k < 4; k++) {
            float4 v = make_float4(acc[k * 4 + 0] * inv, acc[k * 4 + 1] * inv,
                                   acc[k * 4 + 2] * inv, acc[k * 4 + 3] * inv);
            *reinterpret_cast<float4*>(&buf[w][g][gl * 16 + k * 4]) = v;
        }
        __syncwarp();

        o4 = make_float4(r4.x + b4.x, r4.y + b4.y, r4.z + b4.z, r4.w + b4.w);
#pragma unroll
        for (int gg = 0; gg < HH; gg++) {
            float4 v = *reinterpret_cast<const float4*>(&buf[w][gg][lane * 4]);
            o4.x += v.x; o4.y += v.y; o4.z += v.z; o4.w += v.w;
        }
        __syncwarp();
    }

    // ================= CG phase (interleaved; one uint4/lane/edge) ========
    {
        const __half* __restrict__ Ps = a.Ps[t];
        const int* __restrict__ row = a.crowp[t];
        const int* __restrict__ srcs = a.csrcs[t];

        float dg[8];
        half8_to_float8(
            *reinterpret_cast<const uint4*>(a.Pd[t] + (size_t)d * LDC + lane * 8), dg);

        const int e0 = row[d], e1 = row[d + 1];

        uint4 cv;
        if (e0 < e1) {
            int sn = srcs[e0];
            cv = *reinterpret_cast<const uint4*>(Ps + (size_t)sn * LDC + lane * 8);
        }
        for (int p = e0; p < e1; p++) {
            uint4 dv = cv;
            if (p + 1 < e1) {
                int sn = srcs[p + 1];
                cv = *reinterpret_cast<const uint4*>(Ps + (size_t)sn * LDC + lane * 8);
            }
            float sg[8];
            half8_to_float8(dv, sg);
            o4.x += gate1(dg[0] + sg[0], dg[4] + sg[4]);
            o4.y += gate1(dg[1] + sg[1], dg[5] + sg[5]);
            o4.z += gate1(dg[2] + sg[2], dg[6] + sg[6]);
            o4.w += gate1(dg[3] + sg[3], dg[7] + sg[7]);
        }
    }

    size_t off = (size_t)d * DD + lane * 4;
    *reinterpret_cast<__half2*>(a.ah[t] + off)     = __floats2half2_rn(o4.x, o4.y);
    *reinterpret_cast<__half2*>(a.ah[t] + off + 2) = __floats2half2_rn(o4.z, o4.w);
}

// ---------------------------------------------------------------------------
// Host launcher
// ---------------------------------------------------------------------------
extern "C" void kernel_launch(void* const* d_in, const int* in_sizes, int n_in,
                              void* d_out, int out_size)
{
    const float* in_x_my  = (const float*)d_in[0];
    const float* in_x_opp = (const float*)d_in[1];
    const float* gWl_b = (const float*)d_in[2];
    const float* gWr_b = (const float*)d_in[3];
    const float* gatt_b = (const float*)d_in[4];
    const float* gb_b  = (const float*)d_in[5];
    const float* gWl_r = (const float*)d_in[6];
    const float* gWr_r = (const float*)d_in[7];
    const float* gatt_r = (const float*)d_in[8];
    const float* gb_r  = (const float*)d_in[9];
    const float* cgL_Wf = (const float*)d_in[10];
    const float* cgL_bf = (const float*)d_in[11];
    const float* cgL_Ws = (const float*)d_in[12];
    const float* cgL_bs = (const float*)d_in[13];
    const float* cgR_Wf = (const float*)d_in[14];
    const float* cgR_bf = (const float*)d_in[15];
    const float* cgR_Ws = (const float*)d_in[16];
    const float* cgR_bs = (const float*)d_in[17];
    const float* nw_W = (const float*)d_in[18];
    const float* nw_b = (const float*)d_in[19];
    const int* ei_beats     = (const int*)d_in[20];
    const int* ei_loses     = (const int*)d_in[21];
    const int* ei_rev_beats = (const int*)d_in[22];
    const int* ei_rev_loses = (const int*)d_in[23];

    float* out = (float*)d_out;

    float *x_my, *x_opp, *bias_b, *bias_ob;
    __half *C_my, *C_opp;
    __half *xh_my, *xh_opp, *ah_my, *ah_opp;
    __half *Wth_mb, *Wth_ob, *nwWhb;
    int *rowp, *cntp, *fillp, *srcsp;
    cudaGetSymbolAddress((void**)&C_my,  g_C_my);
    cudaGetSymbolAddress((void**)&C_opp, g_C_opp);
    cudaGetSymbolAddress((void**)&x_my,  g_x_my);
    cudaGetSymbolAddress((void**)&x_opp, g_x_opp);
    cudaGetSymbolAddress((void**)&bias_b,  g_bias_my);
    cudaGetSymbolAddress((void**)&bias_ob, g_bias_opp);
    cudaGetSymbolAddress((void**)&xh_my,  g_xh_my);
    cudaGetSymbolAddress((void**)&xh_opp, g_xh_opp);
    cudaGetSymbolAddress((void**)&ah_my,  g_ah_my);
    cudaGetSymbolAddress((void**)&ah_opp, g_ah_opp);
    cudaGetSymbolAddress((void**)&Wth_mb,  g_Wth_my);
    cudaGetSymbolAddress((void**)&Wth_ob, g_Wth_opp);
    cudaGetSymbolAddress((void**)&nwWhb, g_nwWh);
    cudaGetSymbolAddress((void**)&rowp,  g_row);
    cudaGetSymbolAddress((void**)&cntp,  g_cnt);
    cudaGetSymbolAddress((void**)&fillp, g_fill);
    cudaGetSymbolAddress((void**)&srcsp, g_srcs);

    cudaFuncSetAttribute(mma_gemm, cudaFuncAttributeMaxDynamicSharedMemorySize,
                         DYN_SMEM);

    // side stream + events (created once, outside any capture)
    static cudaStream_t s2 = nullptr;
    static cudaEvent_t evFork = nullptr, evCsr = nullptr, evPrep1 = nullptr;
    if (!s2) {
        cudaStreamCreateWithFlags(&s2, cudaStreamNonBlocking);
        cudaEventCreateWithFlags(&evFork,  cudaEventDisableTiming);
        cudaEventCreateWithFlags(&evCsr,   cudaEventDisableTiming);
        cudaEventCreateWithFlags(&evPrep1, cudaEventDisableTiming);
    }

    const int* src_b  = ei_beats;      const int* dst_b  = ei_beats + EE;
    const int* src_l  = ei_loses;      const int* dst_l  = ei_loses + EE;
    const int* src_rb = ei_rev_beats;  const int* dst_rb = ei_rev_beats + EE;
    const int* src_rl = ei_rev_loses;  const int* dst_rl = ei_rev_loses + EE;

    const int node_blocks = (NN + 7) / 8;
    const int e_blocks    = (EE + 255) / 256;
    const int mtiles      = (NN + 127) / 128;      // 157

    __half* Wth_my_l[2]  = { Wth_mb,  Wth_mb + DD * LDC };
    __half* Wth_opp_l[2] = { Wth_ob,  Wth_ob + DD * LDC };
    __half* nwWh_l[2]    = { nwWhb,   nwWhb + DD * DD };
    float*  bias_my_l[2] = { bias_b,  bias_b + LDC };
    float*  bias_opp_l[2]= { bias_ob, bias_ob + LDC };

    // ---- fork side stream (R15 schedule) ----
    cudaEventRecord(evFork, 0);
    cudaStreamWaitEvent(s2, evFork, 0);

    // side stream: CSR build, then layer-1 weight prep
    csr_zero_kernel<<<(4 * NN + 255) / 256, 256, 0, s2>>>(cntp, fillp);
    csr_hist_kernel<<<e_blocks, 256, 0, s2>>>(dst_b, dst_rl, dst_l, dst_rb, cntp);
    csr_scan_kernel<<<4, 1024, 0, s2>>>(cntp, rowp);
    csr_scatter_kernel<<<e_blocks, 256, 0, s2>>>(src_b, dst_b, src_rl, dst_rl,
                                                 src_l, dst_l, src_rb, dst_rb,
                                                 rowp, fillp, srcsp);
    cudaEventRecord(evCsr, s2);
    {
        const size_t oW = (size_t)1 * DD * HD;
        const size_t oB = (size_t)1 * DD;
        const size_t oC = (size_t)1 * 2 * DD * DD;
        const size_t oN = (size_t)1 * DD * DD;
        prep_all_kernel<<<(DD * LDC + 255) / 256, 256, 0, s2>>>(
            gWl_b + oW, gWr_b + oW, gWl_r + oW, gWr_r + oW,
            cgL_Wf + oC, cgL_Ws + oC, cgR_Wf + oC, cgR_Ws + oC,
            cgL_bf + oB, cgL_bs + oB, cgR_bf + oB, cgR_bs + oB,
            nw_W + oN,
            Wth_my_l[1], Wth_opp_l[1], nwWh_l[1],
            bias_my_l[1], bias_opp_l[1]);
    }
    cudaEventRecord(evPrep1, s2);

    // main stream: input splits + layer-0 weight prep (as in R15)
    split2_half_kernel<<<(2 * NN * DD + 255) / 256, 256>>>(
        in_x_my, in_x_opp, xh_my, xh_opp);
    prep_all_kernel<<<(DD * LDC + 255) / 256, 256>>>(
        gWl_b, gWr_b, gWl_r, gWr_r,
        cgL_Wf, cgL_Ws, cgR_Wf, cgR_Ws,
        cgL_bf, cgL_bs, cgR_bf, cgR_bs,
        nw_W,
        Wth_my_l[0], Wth_opp_l[0], nwWh_l[0],
        bias_my_l[0], bias_opp_l[0]);

    const float* cur_my  = in_x_my;
    const float* cur_opp = in_x_opp;

    for (int l = 0; l < LLAYERS; l++) {
        const size_t oA = (size_t)l * HH * DD;
        const size_t oB = (size_t)l * DD;

        if (l > 0) cudaStreamWaitEvent(0, evPrep1, 0);

        // ---- fat projection GEMMs ----
        {
            GemmArgs ga;
            ga.Ah[0] = xh_my;   ga.Ah[1] = xh_opp;
            ga.Bh[0] = Wth_my_l[l];  ga.Bh[1] = Wth_opp_l[l];
            ga.bias[0] = bias_my_l[l];  ga.bias[1] = bias_opp_l[l];
            ga.Ch[0] = C_my;    ga.Ch[1] = C_opp;
            ga.Cf[0] = nullptr; ga.Cf[1] = nullptr;
            ga.Hout[0] = nullptr; ga.Hout[1] = nullptr;
            ga.M = NN; ga.ldc = LDC; ga.ldb = LDC;
            dim3 grid(LDC / 128, mtiles, 2);
            mma_gemm<<<grid, 256, DYN_SMEM>>>(ga);
        }

        if (l == 0) cudaStreamWaitEvent(0, evCsr, 0);

        // ---- fused edge phase: GAT + CG per dst type, one launch ----
        {
            EdgeArgs a;
            // t=0: dst opp — GAT beats (rel 0), CG lose interleaved (rel 2)
            a.xl[0] = C_my;        a.xr[0] = C_opp;
            a.att[0] = gatt_b + oA;
            a.growp[0] = rowp + 0 * (NN + 1);  a.gsrcs[0] = srcsp + 0 * EE;
            a.Pd[0] = C_opp + 1024; a.Ps[0] = C_my + 1024;
            a.crowp[0] = rowp + 2 * (NN + 1);  a.csrcs[0] = srcsp + 2 * EE;
            a.xres[0] = cur_opp;   a.bias[0] = gb_b + oB;  a.ah[0] = ah_opp;
            // t=1: dst my — GAT rev_loses (rel 1), CG rev interleaved (rel 3)
            a.xl[1] = C_opp + 512; a.xr[1] = C_my + 512;
            a.att[1] = gatt_r + oA;
            a.growp[1] = rowp + 1 * (NN + 1);  a.gsrcs[1] = srcsp + 1 * EE;
            a.Pd[1] = C_my + 1280; a.Ps[1] = C_opp + 1280;
            a.crowp[1] = rowp + 3 * (NN + 1);  a.csrcs[1] = srcsp + 3 * EE;
            a.xres[1] = cur_my;    a.bias[1] = gb_r + oB;  a.ah[1] = ah_my;
            dim3 grid(node_blocks, 2);
            edge_fused_kernel<<<grid, 256>>>(a);
        }

        // ---- nodewise Linear (both node types, one launch; fp32 out) ----
        {
            float* out_my  = (l == LLAYERS - 1) ? out           : x_my;
            float* out_opp = (l == LLAYERS - 1) ? out + NN * DD : x_opp;
            bool last = (l == LLAYERS - 1);
            GemmArgs ga;
            ga.Ah[0] = ah_my;   ga.Ah[1] = ah_opp;
            ga.Bh[0] = nwWh_l[l];  ga.Bh[1] = nwWh_l[l];
            ga.bias[0] = nw_b + oB;  ga.bias[1] = nw_b + oB;
            ga.Ch[0] = nullptr; ga.Ch[1] = nullptr;
            ga.Cf[0] = out_my;  ga.Cf[1] = out_opp;
            ga.Hout[0] = last ? nullptr : xh_my;
            ga.Hout[1] = last ? nullptr : xh_opp;
            ga.M = NN; ga.ldc = DD; ga.ldb = DD;
            dim3 grid(1, mtiles, 2);
            mma_gemm<<<grid, 256, DYN_SMEM>>>(ga);
        }

        cur_my  = x_my;
        cur_opp = x_opp;
    }
}